// round 4
// baseline (speedup 1.0000x reference)
#include <cuda_runtime.h>
#include <cuda_bf16.h>
#include <math.h>
#include <stdint.h>

#define T_TOK 2048
#define H_DIM 2048
#define I_DIM 2048
#define E_NUM 16
#define TOPK  4
#define ROWS  (T_TOK*TOPK)

// ---------------- scratch ----------------
__device__ __nv_bfloat16 g_tnhi[(size_t)T_TOK * H_DIM];
__device__ __nv_bfloat16 g_tnlo[(size_t)T_TOK * H_DIM];
__device__ __nv_bfloat16 g_w1hi[(size_t)E_NUM * 2 * I_DIM * H_DIM];
__device__ __nv_bfloat16 g_w1lo[(size_t)E_NUM * 2 * I_DIM * H_DIM];
__device__ __nv_bfloat16 g_w2hi[(size_t)E_NUM * H_DIM * I_DIM];
__device__ __nv_bfloat16 g_w2lo[(size_t)E_NUM * H_DIM * I_DIM];
__device__ __nv_bfloat16 g_h1hi[(size_t)ROWS * I_DIM];
__device__ __nv_bfloat16 g_h1lo[(size_t)ROWS * I_DIM];
__device__ float g_h2[(size_t)ROWS * H_DIM];
__device__ int   g_cnt[E_NUM];
__device__ int   g_cnt2[E_NUM];
__device__ int   g_off[E_NUM];
__device__ int   g_rowtok[ROWS];
__device__ float g_roww[ROWS];
__device__ int   g_tokrows[T_TOK * TOPK];
__device__ int   g_topidx[T_TOK * TOPK];
__device__ float g_topw[T_TOK * TOPK];

// ---------------- PTX helpers (base compute_103 ISA only) ----------------
__device__ __forceinline__ uint32_t smem_u32(const void* p) {
    uint32_t a;
    asm("{ .reg .u64 t; cvta.to.shared.u64 t, %1; cvt.u32.u64 %0, t; }" : "=r"(a) : "l"(p));
    return a;
}
__device__ __forceinline__ void ldsm_x4(uint32_t* r, uint32_t addr) {
    asm volatile("ldmatrix.sync.aligned.m8n8.x4.shared.b16 {%0,%1,%2,%3}, [%4];"
                 : "=r"(r[0]), "=r"(r[1]), "=r"(r[2]), "=r"(r[3]) : "r"(addr));
}
__device__ __forceinline__ void mma16816(float* d, const uint32_t* a, const uint32_t* b) {
    asm volatile("mma.sync.aligned.m16n8k16.row.col.f32.bf16.bf16.f32 "
                 "{%0,%1,%2,%3}, {%4,%5,%6,%7}, {%8,%9}, {%0,%1,%2,%3};"
                 : "+f"(d[0]), "+f"(d[1]), "+f"(d[2]), "+f"(d[3])
                 : "r"(a[0]), "r"(a[1]), "r"(a[2]), "r"(a[3]), "r"(b[0]), "r"(b[1]));
}

// ---------------- 0: init ----------------
__global__ void init_kernel() {
    int i = threadIdx.x;
    if (i < E_NUM) { g_cnt[i] = 0; g_cnt2[i] = 0; }
}

// ---------------- 1: fused RMSNorm + router (writes bf16 hi/lo) ----------------
__global__ __launch_bounds__(256) void rms_router_kernel(
    const float* __restrict__ x, const float* __restrict__ scale,
    const float* __restrict__ gk, const float* __restrict__ gb)
{
    int t = blockIdx.x;
    int tid = threadIdx.x;
    const float* xr = x + (size_t)t * H_DIM;

    float4 v0 = *(const float4*)(xr + tid * 8);
    float4 v1 = *(const float4*)(xr + tid * 8 + 4);
    float ss = v0.x*v0.x + v0.y*v0.y + v0.z*v0.z + v0.w*v0.w
             + v1.x*v1.x + v1.y*v1.y + v1.z*v1.z + v1.w*v1.w;
    #pragma unroll
    for (int o = 16; o > 0; o >>= 1) ss += __shfl_down_sync(0xffffffffu, ss, o);
    __shared__ float warpsum[8];
    __shared__ float s_r;
    if ((tid & 31) == 0) warpsum[tid >> 5] = ss;
    __syncthreads();
    if (tid == 0) {
        float tot = 0.f;
        #pragma unroll
        for (int w = 0; w < 8; w++) tot += warpsum[w];
        s_r = 1.0f / sqrtf(tot / (float)H_DIM + 1e-5f);
    }
    __syncthreads();
    float r = s_r;

    float4 sc0 = *(const float4*)(scale + tid * 8);
    float4 sc1 = *(const float4*)(scale + tid * 8 + 4);
    float tn[8];
    tn[0] = v0.x*r*sc0.x; tn[1] = v0.y*r*sc0.y; tn[2] = v0.z*r*sc0.z; tn[3] = v0.w*r*sc0.w;
    tn[4] = v1.x*r*sc1.x; tn[5] = v1.y*r*sc1.y; tn[6] = v1.z*r*sc1.z; tn[7] = v1.w*r*sc1.w;

    __nv_bfloat162 hh[4], ll[4];
    #pragma unroll
    for (int u = 0; u < 4; u++) {
        float a = tn[2*u], b = tn[2*u+1];
        __nv_bfloat16 ah = __float2bfloat16(a), bh = __float2bfloat16(b);
        hh[u].x = ah; hh[u].y = bh;
        ll[u].x = __float2bfloat16(a - __bfloat162float(ah));
        ll[u].y = __float2bfloat16(b - __bfloat162float(bh));
    }
    size_t toff = (size_t)t * H_DIM + tid * 8;
    *(uint4*)(g_tnhi + toff) = *(uint4*)hh;
    *(uint4*)(g_tnlo + toff) = *(uint4*)ll;

    float ge[E_NUM];
    #pragma unroll
    for (int e = 0; e < E_NUM; e++) ge[e] = 0.f;
    #pragma unroll
    for (int u = 0; u < 8; u++) {
        const float4* wrow = (const float4*)(gk + (size_t)(tid * 8 + u) * E_NUM);
        float tv = tn[u];
        float4 a = wrow[0], b = wrow[1], c = wrow[2], d = wrow[3];
        ge[0]+=tv*a.x; ge[1]+=tv*a.y; ge[2]+=tv*a.z; ge[3]+=tv*a.w;
        ge[4]+=tv*b.x; ge[5]+=tv*b.y; ge[6]+=tv*b.z; ge[7]+=tv*b.w;
        ge[8]+=tv*c.x; ge[9]+=tv*c.y; ge[10]+=tv*c.z; ge[11]+=tv*c.w;
        ge[12]+=tv*d.x; ge[13]+=tv*d.y; ge[14]+=tv*d.z; ge[15]+=tv*d.w;
    }
    #pragma unroll
    for (int o = 16; o > 0; o >>= 1) {
        #pragma unroll
        for (int e = 0; e < E_NUM; e++) ge[e] += __shfl_down_sync(0xffffffffu, ge[e], o);
    }
    __shared__ float sg[8][E_NUM];
    if ((tid & 31) == 0) {
        #pragma unroll
        for (int e = 0; e < E_NUM; e++) sg[tid >> 5][e] = ge[e];
    }
    __syncthreads();
    __shared__ float s_logit[E_NUM];
    if (tid < E_NUM) {
        float v = gb[tid];
        #pragma unroll
        for (int w = 0; w < 8; w++) v += sg[w][tid];
        s_logit[tid] = v;
    }
    __syncthreads();
    if (tid == 0) {
        float vals[E_NUM];
        #pragma unroll
        for (int e = 0; e < E_NUM; e++) vals[e] = s_logit[e];
        int ids[TOPK]; float tv[TOPK];
        #pragma unroll
        for (int k = 0; k < TOPK; k++) {
            int bi = 0; float bv = -1e30f;
            #pragma unroll
            for (int e = 0; e < E_NUM; e++) if (vals[e] > bv) { bv = vals[e]; bi = e; }
            ids[k] = bi; tv[k] = bv; vals[bi] = -1e30f;
        }
        float m = tv[0], ex[TOPK], s = 0.f;
        #pragma unroll
        for (int k = 0; k < TOPK; k++) { ex[k] = expf(tv[k] - m); s += ex[k]; }
        float inv = 1.0f / s;
        #pragma unroll
        for (int k = 0; k < TOPK; k++) {
            g_topidx[t * TOPK + k] = ids[k];
            g_topw[t * TOPK + k]   = ex[k] * inv;
            atomicAdd(&g_cnt[ids[k]], 1);
        }
    }
}

// ---------------- 2/3: scan + scatter ----------------
__global__ void scan_kernel() {
    if (threadIdx.x == 0) {
        int acc = 0;
        for (int e = 0; e < E_NUM; e++) { g_off[e] = acc; acc += g_cnt[e]; g_cnt2[e] = 0; }
    }
}
__global__ void scatter_kernel() {
    int t = blockIdx.x * blockDim.x + threadIdx.x;
    if (t >= T_TOK) return;
    #pragma unroll
    for (int k = 0; k < TOPK; k++) {
        int e = g_topidx[t * TOPK + k];
        int pos = g_off[e] + atomicAdd(&g_cnt2[e], 1);
        g_rowtok[pos] = t;
        g_roww[pos]   = g_topw[t * TOPK + k];
        g_tokrows[t * TOPK + k] = pos;
    }
}

// ---------------- 4: fp32 -> bf16 hi/lo weight conversion ----------------
__global__ __launch_bounds__(256) void convert_kernel(
    const float* __restrict__ src, __nv_bfloat16* __restrict__ hi,
    __nv_bfloat16* __restrict__ lo, int n4)
{
    int i = blockIdx.x * blockDim.x + threadIdx.x;
    if (i >= n4) return;
    float4 v = ((const float4*)src)[i];
    __nv_bfloat162 h0, h1, l0, l1;
    h0.x = __float2bfloat16(v.x); h0.y = __float2bfloat16(v.y);
    h1.x = __float2bfloat16(v.z); h1.y = __float2bfloat16(v.w);
    l0.x = __float2bfloat16(v.x - __bfloat162float(h0.x));
    l0.y = __float2bfloat16(v.y - __bfloat162float(h0.y));
    l1.x = __float2bfloat16(v.z - __bfloat162float(h1.x));
    l1.y = __float2bfloat16(v.w - __bfloat162float(h1.y));
    ((__nv_bfloat162*)hi)[2*i]   = h0;
    ((__nv_bfloat162*)hi)[2*i+1] = h1;
    ((__nv_bfloat162*)lo)[2*i]   = l0;
    ((__nv_bfloat162*)lo)[2*i+1] = l1;
}

// ---------------- 5/6: grouped GEMMs via mma.sync, bf16 operands pre-split ----------------
// Tile 128x128x32. 8 warps 2(m) x 4(n), warp tile 64x32, 3-term split.
// Smem rows: 32 bf16 = 64B data, padded to 80B pitch.
#define ROWB 80
#define SM_AHI 0
#define SM_ALO 10240
#define SM_BHI 20480
#define SM_BLO 30720
#define SM_TOT 40960

template <int MODE>
__global__ __launch_bounds__(256) void moe_mma_kernel(
    const __nv_bfloat16* __restrict__ Whi, const __nv_bfloat16* __restrict__ Wlo,
    const float* __restrict__ bias)
{
    constexpr int NTOT = (MODE == 1) ? 2 * I_DIM : H_DIM;
    constexpr int KD = 2048;
    constexpr int NST = KD / 32;   // 64 stages

    int mt = blockIdx.y;
    int e = -1, cnt_e = 0, off_e = 0, acc0 = 0;
    #pragma unroll
    for (int ee = 0; ee < E_NUM; ee++) {
        int c = g_cnt[ee];
        int tl = (c + 127) >> 7;
        if (e < 0) {
            if (mt < acc0 + tl) { e = ee; cnt_e = c; off_e = g_off[ee]; mt -= acc0; }
            else acc0 += tl;
        }
    }
    if (e < 0) return;
    int m0 = mt * 128;
    int bn0 = blockIdx.x * 128;

    __shared__ __align__(16) char sm[SM_TOT];
    uint32_t sbase = smem_u32(sm);

    int tid = threadIdx.x;
    int lane = tid & 31;
    int wid = tid >> 5;
    int wm = wid & 1;
    int wn = wid >> 1;

    // per-thread LDG slots: 2 chunks of 16B per array (Ahi,Alo,Bhi,Blo)
    const __nv_bfloat16* aHp[2];
    const __nv_bfloat16* aLp[2];
    const __nv_bfloat16* bHp[2];
    const __nv_bfloat16* bLp[2];
    uint32_t stoff[2];
    #pragma unroll
    for (int t = 0; t < 2; t++) {
        int cid = tid + t * 256;          // 0..511
        int row = cid >> 2;               // 0..127
        int c16 = cid & 3;                // 16B chunk (8 bf16)
        stoff[t] = (uint32_t)(row * ROWB + c16 * 16);
        int lm = m0 + row;
        int safe = (lm < cnt_e) ? lm : 0;
        if (MODE == 1) {
            int tok = g_rowtok[off_e + safe];
            aHp[t] = g_tnhi + (size_t)tok * KD + c16 * 8;
            aLp[t] = g_tnlo + (size_t)tok * KD + c16 * 8;
        } else {
            aHp[t] = g_h1hi + (size_t)(off_e + safe) * KD + c16 * 8;
            aLp[t] = g_h1lo + (size_t)(off_e + safe) * KD + c16 * 8;
        }
        size_t wrow = ((size_t)e * NTOT + bn0 + row) * KD + c16 * 8;
        bHp[t] = Whi + wrow;
        bLp[t] = Wlo + wrow;
    }

    // ldmatrix lane addresses
    uint32_t aoff = (uint32_t)((wm * 64 + (lane & 15)) * ROWB + (lane >> 4) * 16);
    // fused B hi/lo x4: lanes 0-15 -> BHI, 16-31 -> BLO; within: row lane&7, k-half (lane>>3)&1
    uint32_t bbase = sbase + ((lane < 16) ? SM_BHI : SM_BLO)
                   + (uint32_t)((wn * 32 + (lane & 7)) * ROWB + ((lane >> 3) & 1) * 16);

    float acc[4][4][4];
    #pragma unroll
    for (int i = 0; i < 4; i++)
        #pragma unroll
        for (int j = 0; j < 4; j++)
            #pragma unroll
            for (int q = 0; q < 4; q++) acc[i][j][q] = 0.f;

    uint4 pAh[2], pAl[2], pBh[2], pBl[2];
    #pragma unroll
    for (int t = 0; t < 2; t++) {
        pAh[t] = *(const uint4*)(aHp[t]);
        pAl[t] = *(const uint4*)(aLp[t]);
        pBh[t] = *(const uint4*)(bHp[t]);
        pBl[t] = *(const uint4*)(bLp[t]);
    }

    for (int kt = 0; kt < NST; kt++) {
        __syncthreads();
        #pragma unroll
        for (int t = 0; t < 2; t++) {
            *(uint4*)(sm + SM_AHI + stoff[t]) = pAh[t];
            *(uint4*)(sm + SM_ALO + stoff[t]) = pAl[t];
            *(uint4*)(sm + SM_BHI + stoff[t]) = pBh[t];
            *(uint4*)(sm + SM_BLO + stoff[t]) = pBl[t];
        }
        __syncthreads();
        if (kt + 1 < NST) {
            int kadv = (kt + 1) * 32;
            #pragma unroll
            for (int t = 0; t < 2; t++) {
                pAh[t] = *(const uint4*)(aHp[t] + kadv);
                pAl[t] = *(const uint4*)(aLp[t] + kadv);
                pBh[t] = *(const uint4*)(bHp[t] + kadv);
                pBl[t] = *(const uint4*)(bLp[t] + kadv);
            }
        }
        #pragma unroll
        for (int ks = 0; ks < 2; ks++) {
            uint32_t ah[4][4], al[4][4];
            #pragma unroll
            for (int im = 0; im < 4; im++) {
                ldsm_x4(ah[im], sbase + SM_AHI + aoff + im * (16 * ROWB) + ks * 32);
                ldsm_x4(al[im], sbase + SM_ALO + aoff + im * (16 * ROWB) + ks * 32);
            }
            #pragma unroll
            for (int in = 0; in < 4; in++) {
                uint32_t bfr[4];   // [0,1] = Bhi k16 frag, [2,3] = Blo k16 frag
                ldsm_x4(bfr, bbase + in * (8 * ROWB) + ks * 32);
                #pragma unroll
                for (int im = 0; im < 4; im++) {
                    mma16816(acc[im][in], ah[im], bfr);       // Ahi * Bhi
                    mma16816(acc[im][in], al[im], bfr);       // Alo * Bhi
                    mma16816(acc[im][in], ah[im], bfr + 2);   // Ahi * Blo
                }
            }
        }
    }

    // ---------------- epilogue ----------------
    #pragma unroll
    for (int im = 0; im < 4; im++) {
        #pragma unroll
        for (int in = 0; in < 4; in++) {
            int r0 = m0 + wm * 64 + im * 16 + (lane >> 2);
            int c  = bn0 + wn * 32 + in * 8 + (lane & 3) * 2;
            const float* bp = bias + (size_t)e * NTOT + c;
            #pragma unroll
            for (int half = 0; half < 2; half++) {
                int r = r0 + half * 8;
                if (r >= cnt_e) continue;
                int p = off_e + r;
                float d0 = acc[im][in][half * 2 + 0];
                float d1 = acc[im][in][half * 2 + 1];
                if (MODE == 1) {
                    float glu = d0 + __ldg(bp);
                    float lin = d1 + __ldg(bp + 1);
                    glu = fminf(glu, 7.0f);
                    lin = fminf(fmaxf(lin, -7.0f), 7.0f);
                    float sig = 1.0f / (1.0f + expf(-1.702f * glu));
                    float h = glu * sig * (lin + 1.0f);
                    __nv_bfloat16 hh = __float2bfloat16(h);
                    size_t idx = (size_t)p * I_DIM + (c >> 1);
                    g_h1hi[idx] = hh;
                    g_h1lo[idx] = __float2bfloat16(h - __bfloat162float(hh));
                } else {
                    float w = g_roww[p];
                    float o0 = (d0 + __ldg(bp)) * w;
                    float o1 = (d1 + __ldg(bp + 1)) * w;
                    *(float2*)&g_h2[(size_t)p * H_DIM + c] = make_float2(o0, o1);
                }
            }
        }
    }
}

// ---------------- 7: combine ----------------
__global__ __launch_bounds__(256) void combine_kernel(
    const float* __restrict__ x, float* __restrict__ out)
{
    int t = blockIdx.x;
    int tid = threadIdx.x;
    int p0 = g_tokrows[t * TOPK + 0];
    int p1 = g_tokrows[t * TOPK + 1];
    int p2 = g_tokrows[t * TOPK + 2];
    int p3 = g_tokrows[t * TOPK + 3];
    const float4* xr = (const float4*)(x + (size_t)t * H_DIM);
    float4* orow = (float4*)(out + (size_t)t * H_DIM);
    const float4* a = (const float4*)(g_h2 + (size_t)p0 * H_DIM);
    const float4* b = (const float4*)(g_h2 + (size_t)p1 * H_DIM);
    const float4* c = (const float4*)(g_h2 + (size_t)p2 * H_DIM);
    const float4* d = (const float4*)(g_h2 + (size_t)p3 * H_DIM);
    #pragma unroll
    for (int r = 0; r < 2; r++) {
        int f = tid + r * 256;
        float4 v = xr[f];
        float4 q0 = a[f], q1 = b[f], q2 = c[f], q3 = d[f];
        v.x += q0.x + q1.x + q2.x + q3.x;
        v.y += q0.y + q1.y + q2.y + q3.y;
        v.z += q0.z + q1.z + q2.z + q3.z;
        v.w += q0.w + q1.w + q2.w + q3.w;
        orow[f] = v;
    }
}

// ---------------- launch ----------------
extern "C" void kernel_launch(void* const* d_in, const int* in_sizes, int n_in,
                              void* d_out, int out_size)
{
    const float* x     = (const float*)d_in[0];
    const float* scale = (const float*)d_in[1];
    const float* gk    = (const float*)d_in[2];
    const float* gb    = (const float*)d_in[3];
    const float* w1    = (const float*)d_in[4];
    const float* b1    = (const float*)d_in[5];
    const float* w2    = (const float*)d_in[6];
    const float* b2    = (const float*)d_in[7];
    float* out = (float*)d_out;

    __nv_bfloat16 *w1hi, *w1lo, *w2hi, *w2lo;
    cudaGetSymbolAddress((void**)&w1hi, g_w1hi);
    cudaGetSymbolAddress((void**)&w1lo, g_w1lo);
    cudaGetSymbolAddress((void**)&w2hi, g_w2hi);
    cudaGetSymbolAddress((void**)&w2lo, g_w2lo);

    init_kernel<<<1, 32>>>();
    rms_router_kernel<<<T_TOK, 256>>>(x, scale, gk, gb);
    scan_kernel<<<1, 32>>>();
    scatter_kernel<<<(T_TOK + 255) / 256, 256>>>();

    int n1 = E_NUM * 2 * I_DIM * H_DIM / 4;
    int n2 = E_NUM * H_DIM * I_DIM / 4;
    convert_kernel<<<n1 / 256, 256>>>(w1, w1hi, w1lo, n1);
    convert_kernel<<<n2 / 256, 256>>>(w2, w2hi, w2lo, n2);

    moe_mma_kernel<1><<<dim3(2 * I_DIM / 128, 80), 256>>>(w1hi, w1lo, b1);
    moe_mma_kernel<2><<<dim3(H_DIM / 128, 80), 256>>>(w2hi, w2lo, b2);
    combine_kernel<<<T_TOK, 256>>>(x, out);
}

// round 5
// speedup vs baseline: 1.3896x; 1.3896x over previous
#include <cuda_runtime.h>
#include <cuda_fp16.h>
#include <math.h>
#include <stdint.h>

#define T_TOK 2048
#define H_DIM 2048
#define I_DIM 2048
#define E_NUM 16
#define TOPK  4
#define ROWS  (T_TOK*TOPK)

// ---------------- scratch ----------------
__device__ __half g_tnhi[(size_t)T_TOK * H_DIM];
__device__ __half g_tnlo[(size_t)T_TOK * H_DIM];
__device__ __half g_w1h[(size_t)E_NUM * 2 * I_DIM * H_DIM];   // 256 MB
__device__ __half g_w2h[(size_t)E_NUM * H_DIM * I_DIM];       // 128 MB
__device__ __half g_h1hi[(size_t)ROWS * I_DIM];
__device__ __half g_h1lo[(size_t)ROWS * I_DIM];
__device__ float g_h2[(size_t)ROWS * H_DIM];
__device__ int   g_cnt[E_NUM];
__device__ int   g_cnt2[E_NUM];
__device__ int   g_off[E_NUM];
__device__ int   g_rowtok[ROWS];
__device__ float g_roww[ROWS];
__device__ int   g_tokrows[T_TOK * TOPK];
__device__ int   g_topidx[T_TOK * TOPK];
__device__ float g_topw[T_TOK * TOPK];

// ---------------- PTX helpers ----------------
__device__ __forceinline__ uint32_t smem_u32(const void* p) {
    uint32_t a;
    asm("{ .reg .u64 t; cvta.to.shared.u64 t, %1; cvt.u32.u64 %0, t; }" : "=r"(a) : "l"(p));
    return a;
}
__device__ __forceinline__ void ldsm_x4(uint32_t* r, uint32_t addr) {
    asm volatile("ldmatrix.sync.aligned.m8n8.x4.shared.b16 {%0,%1,%2,%3}, [%4];"
                 : "=r"(r[0]), "=r"(r[1]), "=r"(r[2]), "=r"(r[3]) : "r"(addr));
}
__device__ __forceinline__ void mma16816(float* d, const uint32_t* a, const uint32_t* b) {
    asm volatile("mma.sync.aligned.m16n8k16.row.col.f32.f16.f16.f32 "
                 "{%0,%1,%2,%3}, {%4,%5,%6,%7}, {%8,%9}, {%0,%1,%2,%3};"
                 : "+f"(d[0]), "+f"(d[1]), "+f"(d[2]), "+f"(d[3])
                 : "r"(a[0]), "r"(a[1]), "r"(a[2]), "r"(a[3]), "r"(b[0]), "r"(b[1]));
}
__device__ __forceinline__ void split_h(float x, __half& hi, __half& lo) {
    hi = __float2half(x);
    lo = __float2half(x - __half2float(hi));
}

// ---------------- 0: init ----------------
__global__ void init_kernel() {
    int i = threadIdx.x;
    if (i < E_NUM) { g_cnt[i] = 0; g_cnt2[i] = 0; }
}

// ---------------- 1: fused RMSNorm + router (writes fp16 hi/lo) ----------------
__global__ __launch_bounds__(256) void rms_router_kernel(
    const float* __restrict__ x, const float* __restrict__ scale,
    const float* __restrict__ gk, const float* __restrict__ gb)
{
    int t = blockIdx.x;
    int tid = threadIdx.x;
    const float* xr = x + (size_t)t * H_DIM;

    float4 v0 = *(const float4*)(xr + tid * 8);
    float4 v1 = *(const float4*)(xr + tid * 8 + 4);
    float ss = v0.x*v0.x + v0.y*v0.y + v0.z*v0.z + v0.w*v0.w
             + v1.x*v1.x + v1.y*v1.y + v1.z*v1.z + v1.w*v1.w;
    #pragma unroll
    for (int o = 16; o > 0; o >>= 1) ss += __shfl_down_sync(0xffffffffu, ss, o);
    __shared__ float warpsum[8];
    __shared__ float s_r;
    if ((tid & 31) == 0) warpsum[tid >> 5] = ss;
    __syncthreads();
    if (tid == 0) {
        float tot = 0.f;
        #pragma unroll
        for (int w = 0; w < 8; w++) tot += warpsum[w];
        s_r = 1.0f / sqrtf(tot / (float)H_DIM + 1e-5f);
    }
    __syncthreads();
    float r = s_r;

    float4 sc0 = *(const float4*)(scale + tid * 8);
    float4 sc1 = *(const float4*)(scale + tid * 8 + 4);
    float tn[8];
    tn[0] = v0.x*r*sc0.x; tn[1] = v0.y*r*sc0.y; tn[2] = v0.z*r*sc0.z; tn[3] = v0.w*r*sc0.w;
    tn[4] = v1.x*r*sc1.x; tn[5] = v1.y*r*sc1.y; tn[6] = v1.z*r*sc1.z; tn[7] = v1.w*r*sc1.w;

    __half hh[8], ll[8];
    #pragma unroll
    for (int u = 0; u < 8; u++) split_h(tn[u], hh[u], ll[u]);
    size_t toff = (size_t)t * H_DIM + tid * 8;
    *(uint4*)(g_tnhi + toff) = *(uint4*)hh;
    *(uint4*)(g_tnlo + toff) = *(uint4*)ll;

    float ge[E_NUM];
    #pragma unroll
    for (int e = 0; e < E_NUM; e++) ge[e] = 0.f;
    #pragma unroll
    for (int u = 0; u < 8; u++) {
        const float4* wrow = (const float4*)(gk + (size_t)(tid * 8 + u) * E_NUM);
        float tv = tn[u];
        float4 a = wrow[0], b = wrow[1], c = wrow[2], d = wrow[3];
        ge[0]+=tv*a.x; ge[1]+=tv*a.y; ge[2]+=tv*a.z; ge[3]+=tv*a.w;
        ge[4]+=tv*b.x; ge[5]+=tv*b.y; ge[6]+=tv*b.z; ge[7]+=tv*b.w;
        ge[8]+=tv*c.x; ge[9]+=tv*c.y; ge[10]+=tv*c.z; ge[11]+=tv*c.w;
        ge[12]+=tv*d.x; ge[13]+=tv*d.y; ge[14]+=tv*d.z; ge[15]+=tv*d.w;
    }
    #pragma unroll
    for (int o = 16; o > 0; o >>= 1) {
        #pragma unroll
        for (int e = 0; e < E_NUM; e++) ge[e] += __shfl_down_sync(0xffffffffu, ge[e], o);
    }
    __shared__ float sg[8][E_NUM];
    if ((tid & 31) == 0) {
        #pragma unroll
        for (int e = 0; e < E_NUM; e++) sg[tid >> 5][e] = ge[e];
    }
    __syncthreads();
    __shared__ float s_logit[E_NUM];
    if (tid < E_NUM) {
        float v = gb[tid];
        #pragma unroll
        for (int w = 0; w < 8; w++) v += sg[w][tid];
        s_logit[tid] = v;
    }
    __syncthreads();
    if (tid == 0) {
        float vals[E_NUM];
        #pragma unroll
        for (int e = 0; e < E_NUM; e++) vals[e] = s_logit[e];
        int ids[TOPK]; float tv[TOPK];
        #pragma unroll
        for (int k = 0; k < TOPK; k++) {
            int bi = 0; float bv = -1e30f;
            #pragma unroll
            for (int e = 0; e < E_NUM; e++) if (vals[e] > bv) { bv = vals[e]; bi = e; }
            ids[k] = bi; tv[k] = bv; vals[bi] = -1e30f;
        }
        float m = tv[0], ex[TOPK], s = 0.f;
        #pragma unroll
        for (int k = 0; k < TOPK; k++) { ex[k] = expf(tv[k] - m); s += ex[k]; }
        float inv = 1.0f / s;
        #pragma unroll
        for (int k = 0; k < TOPK; k++) {
            g_topidx[t * TOPK + k] = ids[k];
            g_topw[t * TOPK + k]   = ex[k] * inv;
            atomicAdd(&g_cnt[ids[k]], 1);
        }
    }
}

// ---------------- 2/3: scan + scatter ----------------
__global__ void scan_kernel() {
    if (threadIdx.x == 0) {
        int acc = 0;
        for (int e = 0; e < E_NUM; e++) { g_off[e] = acc; acc += g_cnt[e]; g_cnt2[e] = 0; }
    }
}
__global__ void scatter_kernel() {
    int t = blockIdx.x * blockDim.x + threadIdx.x;
    if (t >= T_TOK) return;
    #pragma unroll
    for (int k = 0; k < TOPK; k++) {
        int e = g_topidx[t * TOPK + k];
        int pos = g_off[e] + atomicAdd(&g_cnt2[e], 1);
        g_rowtok[pos] = t;
        g_roww[pos]   = g_topw[t * TOPK + k];
        g_tokrows[t * TOPK + k] = pos;
    }
}

// ---------------- 4: fp32 -> fp16 (single) weight conversion ----------------
__global__ __launch_bounds__(256) void convert_kernel(
    const float* __restrict__ src, __half* __restrict__ dst, int n4)
{
    int i = blockIdx.x * blockDim.x + threadIdx.x;
    if (i >= n4) return;
    float4 v = ((const float4*)src)[i];
    __half2 h0, h1;
    h0.x = __float2half(v.x); h0.y = __float2half(v.y);
    h1.x = __float2half(v.z); h1.y = __float2half(v.w);
    ((__half2*)dst)[2*i]   = h0;
    ((__half2*)dst)[2*i+1] = h1;
}

// ---------------- 5/6: grouped GEMMs via mma.sync fp16, A split, B single ----------------
// Tile 128x128x32.  8 warps 2(m) x 4(n), warp tile 64x32.
// D = Ah*B + Al*B.  64 HMMA / warp / stage.  Double-buffered smem.
// Per-buffer: AHI [0,10240)  ALO [10240,20480)  B [20480,30720). Pitch 80B.
#define ROWB 80
#define SM_AHI 0
#define SM_ALO 10240
#define SM_B   20480
#define BUF_BYTES 30720
#define DSMEM (2 * BUF_BYTES)

template <int MODE>
__global__ __launch_bounds__(256) void moe_mma_kernel(
    const __half* __restrict__ W, const float* __restrict__ bias)
{
    constexpr int NTOT = (MODE == 1) ? 2 * I_DIM : H_DIM;
    constexpr int KD = 2048;
    constexpr int NST = KD / 32;   // 64 stages

    int mt = blockIdx.y;
    int e = -1, cnt_e = 0, off_e = 0, acc0 = 0;
    #pragma unroll
    for (int ee = 0; ee < E_NUM; ee++) {
        int c = g_cnt[ee];
        int tl = (c + 127) >> 7;
        if (e < 0) {
            if (mt < acc0 + tl) { e = ee; cnt_e = c; off_e = g_off[ee]; mt -= acc0; }
            else acc0 += tl;
        }
    }
    if (e < 0) return;
    int m0 = mt * 128;
    int bn0 = blockIdx.x * 128;

    extern __shared__ __align__(16) char sm[];
    uint32_t sbase = smem_u32(sm);

    int tid = threadIdx.x;
    int lane = tid & 31;
    int wid = tid >> 5;
    int wm = wid & 1;
    int wn = wid >> 1;

    // per-thread LDG slots: 2 x 16B chunks per array (Ahi, Alo, B)
    const __half* aHp[2];
    const __half* aLp[2];
    const __half* bP[2];
    uint32_t stoff[2];
    #pragma unroll
    for (int t = 0; t < 2; t++) {
        int cid = tid + t * 256;          // 0..511
        int row = cid >> 2;               // 0..127
        int c16 = cid & 3;                // 16B chunk (8 halves)
        stoff[t] = (uint32_t)(row * ROWB + c16 * 16);
        int lm = m0 + row;
        int safe = (lm < cnt_e) ? lm : 0;
        if (MODE == 1) {
            int tok = g_rowtok[off_e + safe];
            aHp[t] = g_tnhi + (size_t)tok * KD + c16 * 8;
            aLp[t] = g_tnlo + (size_t)tok * KD + c16 * 8;
        } else {
            aHp[t] = g_h1hi + (size_t)(off_e + safe) * KD + c16 * 8;
            aLp[t] = g_h1lo + (size_t)(off_e + safe) * KD + c16 * 8;
        }
        bP[t] = W + ((size_t)e * NTOT + bn0 + row) * KD + c16 * 8;
    }

    // ldmatrix lane addresses
    uint32_t aoff = (uint32_t)((wm * 64 + (lane & 15)) * ROWB + (lane >> 4) * 16);
    // B x4 covers two adjacent n-blocks: lanes 0-15 -> block in2*2, lanes 16-31 -> in2*2+1
    uint32_t boff = (uint32_t)((wn * 32 + (lane & 7) + (lane >> 4) * 8) * ROWB
                               + ((lane >> 3) & 1) * 16);

    float acc[4][4][4];
    #pragma unroll
    for (int i = 0; i < 4; i++)
        #pragma unroll
        for (int j = 0; j < 4; j++)
            #pragma unroll
            for (int q = 0; q < 4; q++) acc[i][j][q] = 0.f;

    uint4 pAh[2], pAl[2], pB[2];
    #pragma unroll
    for (int t = 0; t < 2; t++) {
        pAh[t] = *(const uint4*)(aHp[t]);
        pAl[t] = *(const uint4*)(aLp[t]);
        pB[t]  = *(const uint4*)(bP[t]);
    }
    // prologue: stage 0 -> buffer 0
    #pragma unroll
    for (int t = 0; t < 2; t++) {
        *(uint4*)(sm + SM_AHI + stoff[t]) = pAh[t];
        *(uint4*)(sm + SM_ALO + stoff[t]) = pAl[t];
        *(uint4*)(sm + SM_B   + stoff[t]) = pB[t];
    }
    __syncthreads();

    for (int kt = 0; kt < NST; kt++) {
        uint32_t cbuf = sbase + (kt & 1) * BUF_BYTES;
        // prefetch next stage
        if (kt + 1 < NST) {
            int kadv = (kt + 1) * 32;
            #pragma unroll
            for (int t = 0; t < 2; t++) {
                pAh[t] = *(const uint4*)(aHp[t] + kadv);
                pAl[t] = *(const uint4*)(aLp[t] + kadv);
                pB[t]  = *(const uint4*)(bP[t]  + kadv);
            }
        }
        // compute on current buffer
        #pragma unroll
        for (int ks = 0; ks < 2; ks++) {
            uint32_t ah[4][4], al[4][4];
            #pragma unroll
            for (int im = 0; im < 4; im++) {
                ldsm_x4(ah[im], cbuf + SM_AHI + aoff + im * (16 * ROWB) + ks * 32);
                ldsm_x4(al[im], cbuf + SM_ALO + aoff + im * (16 * ROWB) + ks * 32);
            }
            #pragma unroll
            for (int in2 = 0; in2 < 2; in2++) {
                uint32_t bfr[4];   // [0,1] n-block 2*in2, [2,3] n-block 2*in2+1
                ldsm_x4(bfr, cbuf + SM_B + boff + in2 * (16 * ROWB) + ks * 32);
                #pragma unroll
                for (int im = 0; im < 4; im++) {
                    mma16816(acc[im][2*in2],   ah[im], bfr);
                    mma16816(acc[im][2*in2],   al[im], bfr);
                    mma16816(acc[im][2*in2+1], ah[im], bfr + 2);
                    mma16816(acc[im][2*in2+1], al[im], bfr + 2);
                }
            }
        }
        // store next stage into the other buffer
        if (kt + 1 < NST) {
            char* nb = sm + ((kt + 1) & 1) * BUF_BYTES;
            #pragma unroll
            for (int t = 0; t < 2; t++) {
                *(uint4*)(nb + SM_AHI + stoff[t]) = pAh[t];
                *(uint4*)(nb + SM_ALO + stoff[t]) = pAl[t];
                *(uint4*)(nb + SM_B   + stoff[t]) = pB[t];
            }
            __syncthreads();
        }
    }

    // ---------------- epilogue ----------------
    #pragma unroll
    for (int im = 0; im < 4; im++) {
        #pragma unroll
        for (int in = 0; in < 4; in++) {
            int r0 = m0 + wm * 64 + im * 16 + (lane >> 2);
            int c  = bn0 + wn * 32 + in * 8 + (lane & 3) * 2;
            const float* bp = bias + (size_t)e * NTOT + c;
            #pragma unroll
            for (int half = 0; half < 2; half++) {
                int r = r0 + half * 8;
                if (r >= cnt_e) continue;
                int p = off_e + r;
                float d0 = acc[im][in][half * 2 + 0];
                float d1 = acc[im][in][half * 2 + 1];
                if (MODE == 1) {
                    float glu = d0 + __ldg(bp);
                    float lin = d1 + __ldg(bp + 1);
                    glu = fminf(glu, 7.0f);
                    lin = fminf(fmaxf(lin, -7.0f), 7.0f);
                    float sig = 1.0f / (1.0f + expf(-1.702f * glu));
                    float h = glu * sig * (lin + 1.0f);
                    __half hh, hl;
                    split_h(h, hh, hl);
                    size_t idx = (size_t)p * I_DIM + (c >> 1);
                    g_h1hi[idx] = hh;
                    g_h1lo[idx] = hl;
                } else {
                    float w = g_roww[p];
                    float o0 = (d0 + __ldg(bp)) * w;
                    float o1 = (d1 + __ldg(bp + 1)) * w;
                    *(float2*)&g_h2[(size_t)p * H_DIM + c] = make_float2(o0, o1);
                }
            }
        }
    }
}

// ---------------- 7: combine ----------------
__global__ __launch_bounds__(256) void combine_kernel(
    const float* __restrict__ x, float* __restrict__ out)
{
    int t = blockIdx.x;
    int tid = threadIdx.x;
    int p0 = g_tokrows[t * TOPK + 0];
    int p1 = g_tokrows[t * TOPK + 1];
    int p2 = g_tokrows[t * TOPK + 2];
    int p3 = g_tokrows[t * TOPK + 3];
    const float4* xr = (const float4*)(x + (size_t)t * H_DIM);
    float4* orow = (float4*)(out + (size_t)t * H_DIM);
    const float4* a = (const float4*)(g_h2 + (size_t)p0 * H_DIM);
    const float4* b = (const float4*)(g_h2 + (size_t)p1 * H_DIM);
    const float4* c = (const float4*)(g_h2 + (size_t)p2 * H_DIM);
    const float4* d = (const float4*)(g_h2 + (size_t)p3 * H_DIM);
    #pragma unroll
    for (int r = 0; r < 2; r++) {
        int f = tid + r * 256;
        float4 v = xr[f];
        float4 q0 = a[f], q1 = b[f], q2 = c[f], q3 = d[f];
        v.x += q0.x + q1.x + q2.x + q3.x;
        v.y += q0.y + q1.y + q2.y + q3.y;
        v.z += q0.z + q1.z + q2.z + q3.z;
        v.w += q0.w + q1.w + q2.w + q3.w;
        orow[f] = v;
    }
}

// ---------------- launch ----------------
extern "C" void kernel_launch(void* const* d_in, const int* in_sizes, int n_in,
                              void* d_out, int out_size)
{
    const float* x     = (const float*)d_in[0];
    const float* scale = (const float*)d_in[1];
    const float* gk    = (const float*)d_in[2];
    const float* gb    = (const float*)d_in[3];
    const float* w1    = (const float*)d_in[4];
    const float* b1    = (const float*)d_in[5];
    const float* w2    = (const float*)d_in[6];
    const float* b2    = (const float*)d_in[7];
    float* out = (float*)d_out;

    __half *w1h, *w2h;
    cudaGetSymbolAddress((void**)&w1h, g_w1h);
    cudaGetSymbolAddress((void**)&w2h, g_w2h);

    static int configured = 0;
    cudaFuncSetAttribute(moe_mma_kernel<1>, cudaFuncAttributeMaxDynamicSharedMemorySize, DSMEM);
    cudaFuncSetAttribute(moe_mma_kernel<2>, cudaFuncAttributeMaxDynamicSharedMemorySize, DSMEM);
    (void)configured;

    init_kernel<<<1, 32>>>();
    rms_router_kernel<<<T_TOK, 256>>>(x, scale, gk, gb);
    scan_kernel<<<1, 32>>>();
    scatter_kernel<<<(T_TOK + 255) / 256, 256>>>();

    int n1 = E_NUM * 2 * I_DIM * H_DIM / 4;
    int n2 = E_NUM * H_DIM * I_DIM / 4;
    convert_kernel<<<n1 / 256, 256>>>(w1, w1h, n1);
    convert_kernel<<<n2 / 256, 256>>>(w2, w2h, n2);

    moe_mma_kernel<1><<<dim3(2 * I_DIM / 128, 80), 256, DSMEM>>>(w1h, b1);
    moe_mma_kernel<2><<<dim3(H_DIM / 128, 80), 256, DSMEM>>>(w2h, b2);
    combine_kernel<<<T_TOK, 256>>>(x, out);
}

// round 6
// speedup vs baseline: 2.3196x; 1.6693x over previous
#include <cuda_runtime.h>
#include <cuda_fp16.h>
#include <math.h>
#include <stdint.h>

#define T_TOK 2048
#define H_DIM 2048
#define I_DIM 2048
#define E_NUM 16
#define TOPK  4
#define ROWS  (T_TOK*TOPK)

// ---------------- scratch ----------------
__device__ __half g_tnh[(size_t)T_TOK * H_DIM];               // 8 MB
__device__ __half g_w1h[(size_t)E_NUM * 2 * I_DIM * H_DIM];   // 256 MB
__device__ __half g_w2h[(size_t)E_NUM * H_DIM * I_DIM];       // 128 MB
__device__ __half g_h1h[(size_t)ROWS * I_DIM];                // 32 MB
__device__ float g_h2[(size_t)ROWS * H_DIM];                  // 64 MB
__device__ int   g_cnt[E_NUM];
__device__ int   g_cnt2[E_NUM];
__device__ int   g_off[E_NUM];
__device__ int   g_rowtok[ROWS];
__device__ float g_roww[ROWS];
__device__ int   g_tokrows[T_TOK * TOPK];
__device__ int   g_topidx[T_TOK * TOPK];
__device__ float g_topw[T_TOK * TOPK];

// ---------------- PTX helpers ----------------
__device__ __forceinline__ uint32_t smem_u32(const void* p) {
    uint32_t a;
    asm("{ .reg .u64 t; cvta.to.shared.u64 t, %1; cvt.u32.u64 %0, t; }" : "=r"(a) : "l"(p));
    return a;
}
__device__ __forceinline__ void ldsm_x4(uint32_t* r, uint32_t addr) {
    asm volatile("ldmatrix.sync.aligned.m8n8.x4.shared.b16 {%0,%1,%2,%3}, [%4];"
                 : "=r"(r[0]), "=r"(r[1]), "=r"(r[2]), "=r"(r[3]) : "r"(addr));
}
__device__ __forceinline__ void mma16816(float* d, const uint32_t* a, const uint32_t* b) {
    asm volatile("mma.sync.aligned.m16n8k16.row.col.f32.f16.f16.f32 "
                 "{%0,%1,%2,%3}, {%4,%5,%6,%7}, {%8,%9}, {%0,%1,%2,%3};"
                 : "+f"(d[0]), "+f"(d[1]), "+f"(d[2]), "+f"(d[3])
                 : "r"(a[0]), "r"(a[1]), "r"(a[2]), "r"(a[3]), "r"(b[0]), "r"(b[1]));
}

// ---------------- 0: init ----------------
__global__ void init_kernel() {
    int i = threadIdx.x;
    if (i < E_NUM) { g_cnt[i] = 0; g_cnt2[i] = 0; }
}

// ---------------- 1: fused RMSNorm + router (writes fp16) ----------------
__global__ __launch_bounds__(256) void rms_router_kernel(
    const float* __restrict__ x, const float* __restrict__ scale,
    const float* __restrict__ gk, const float* __restrict__ gb)
{
    int t = blockIdx.x;
    int tid = threadIdx.x;
    const float* xr = x + (size_t)t * H_DIM;

    float4 v0 = *(const float4*)(xr + tid * 8);
    float4 v1 = *(const float4*)(xr + tid * 8 + 4);
    float ss = v0.x*v0.x + v0.y*v0.y + v0.z*v0.z + v0.w*v0.w
             + v1.x*v1.x + v1.y*v1.y + v1.z*v1.z + v1.w*v1.w;
    #pragma unroll
    for (int o = 16; o > 0; o >>= 1) ss += __shfl_down_sync(0xffffffffu, ss, o);
    __shared__ float warpsum[8];
    __shared__ float s_r;
    if ((tid & 31) == 0) warpsum[tid >> 5] = ss;
    __syncthreads();
    if (tid == 0) {
        float tot = 0.f;
        #pragma unroll
        for (int w = 0; w < 8; w++) tot += warpsum[w];
        s_r = 1.0f / sqrtf(tot / (float)H_DIM + 1e-5f);
    }
    __syncthreads();
    float r = s_r;

    float4 sc0 = *(const float4*)(scale + tid * 8);
    float4 sc1 = *(const float4*)(scale + tid * 8 + 4);
    float tn[8];
    tn[0] = v0.x*r*sc0.x; tn[1] = v0.y*r*sc0.y; tn[2] = v0.z*r*sc0.z; tn[3] = v0.w*r*sc0.w;
    tn[4] = v1.x*r*sc1.x; tn[5] = v1.y*r*sc1.y; tn[6] = v1.z*r*sc1.z; tn[7] = v1.w*r*sc1.w;

    __half hh[8];
    #pragma unroll
    for (int u = 0; u < 8; u++) hh[u] = __float2half(tn[u]);
    *(uint4*)(g_tnh + (size_t)t * H_DIM + tid * 8) = *(uint4*)hh;

    float ge[E_NUM];
    #pragma unroll
    for (int e = 0; e < E_NUM; e++) ge[e] = 0.f;
    #pragma unroll
    for (int u = 0; u < 8; u++) {
        const float4* wrow = (const float4*)(gk + (size_t)(tid * 8 + u) * E_NUM);
        float tv = tn[u];
        float4 a = wrow[0], b = wrow[1], c = wrow[2], d = wrow[3];
        ge[0]+=tv*a.x; ge[1]+=tv*a.y; ge[2]+=tv*a.z; ge[3]+=tv*a.w;
        ge[4]+=tv*b.x; ge[5]+=tv*b.y; ge[6]+=tv*b.z; ge[7]+=tv*b.w;
        ge[8]+=tv*c.x; ge[9]+=tv*c.y; ge[10]+=tv*c.z; ge[11]+=tv*c.w;
        ge[12]+=tv*d.x; ge[13]+=tv*d.y; ge[14]+=tv*d.z; ge[15]+=tv*d.w;
    }
    #pragma unroll
    for (int o = 16; o > 0; o >>= 1) {
        #pragma unroll
        for (int e = 0; e < E_NUM; e++) ge[e] += __shfl_down_sync(0xffffffffu, ge[e], o);
    }
    __shared__ float sg[8][E_NUM];
    if ((tid & 31) == 0) {
        #pragma unroll
        for (int e = 0; e < E_NUM; e++) sg[tid >> 5][e] = ge[e];
    }
    __syncthreads();
    __shared__ float s_logit[E_NUM];
    if (tid < E_NUM) {
        float v = gb[tid];
        #pragma unroll
        for (int w = 0; w < 8; w++) v += sg[w][tid];
        s_logit[tid] = v;
    }
    __syncthreads();
    if (tid == 0) {
        float vals[E_NUM];
        #pragma unroll
        for (int e = 0; e < E_NUM; e++) vals[e] = s_logit[e];
        int ids[TOPK]; float tv[TOPK];
        #pragma unroll
        for (int k = 0; k < TOPK; k++) {
            int bi = 0; float bv = -1e30f;
            #pragma unroll
            for (int e = 0; e < E_NUM; e++) if (vals[e] > bv) { bv = vals[e]; bi = e; }
            ids[k] = bi; tv[k] = bv; vals[bi] = -1e30f;
        }
        float m = tv[0], ex[TOPK], s = 0.f;
        #pragma unroll
        for (int k = 0; k < TOPK; k++) { ex[k] = expf(tv[k] - m); s += ex[k]; }
        float inv = 1.0f / s;
        #pragma unroll
        for (int k = 0; k < TOPK; k++) {
            g_topidx[t * TOPK + k] = ids[k];
            g_topw[t * TOPK + k]   = ex[k] * inv;
            atomicAdd(&g_cnt[ids[k]], 1);
        }
    }
}

// ---------------- 2/3: scan + scatter ----------------
__global__ void scan_kernel() {
    if (threadIdx.x == 0) {
        int acc = 0;
        for (int e = 0; e < E_NUM; e++) { g_off[e] = acc; acc += g_cnt[e]; g_cnt2[e] = 0; }
    }
}
__global__ void scatter_kernel() {
    int t = blockIdx.x * blockDim.x + threadIdx.x;
    if (t >= T_TOK) return;
    #pragma unroll
    for (int k = 0; k < TOPK; k++) {
        int e = g_topidx[t * TOPK + k];
        int pos = g_off[e] + atomicAdd(&g_cnt2[e], 1);
        g_rowtok[pos] = t;
        g_roww[pos]   = g_topw[t * TOPK + k];
        g_tokrows[t * TOPK + k] = pos;
    }
}

// ---------------- 4: fp32 -> fp16 weight conversion ----------------
__global__ __launch_bounds__(256) void convert_kernel(
    const float* __restrict__ src, __half* __restrict__ dst, int n4)
{
    int i = blockIdx.x * blockDim.x + threadIdx.x;
    if (i >= n4) return;
    float4 v = ((const float4*)src)[i];
    __half2 h0, h1;
    h0.x = __float2half(v.x); h0.y = __float2half(v.y);
    h1.x = __float2half(v.z); h1.y = __float2half(v.w);
    ((__half2*)dst)[2*i]   = h0;
    ((__half2*)dst)[2*i+1] = h1;
}

// ---------------- 5/6: grouped GEMMs via mma.sync fp16 (single pass) ----------------
// Tile 128x128x32.  8 warps 2(m) x 4(n), warp tile 64x32. 32 HMMA/warp/stage.
// Per-buffer: A [0,10240)  B [10240,20480). Pitch 80B. Double-buffered.
#define ROWB 80
#define SM_A 0
#define SM_B 10240
#define BUF_BYTES 20480
#define DSMEM (2 * BUF_BYTES)

template <int MODE>
__global__ __launch_bounds__(256) void moe_mma_kernel(
    const __half* __restrict__ W, const float* __restrict__ bias)
{
    constexpr int NTOT = (MODE == 1) ? 2 * I_DIM : H_DIM;
    constexpr int KD = 2048;
    constexpr int NST = KD / 32;   // 64 stages

    int mt = blockIdx.y;
    int e = -1, cnt_e = 0, off_e = 0, acc0 = 0;
    #pragma unroll
    for (int ee = 0; ee < E_NUM; ee++) {
        int c = g_cnt[ee];
        int tl = (c + 127) >> 7;
        if (e < 0) {
            if (mt < acc0 + tl) { e = ee; cnt_e = c; off_e = g_off[ee]; mt -= acc0; }
            else acc0 += tl;
        }
    }
    if (e < 0) return;
    int m0 = mt * 128;
    int bn0 = blockIdx.x * 128;

    extern __shared__ __align__(16) char sm[];
    uint32_t sbase = smem_u32(sm);

    int tid = threadIdx.x;
    int lane = tid & 31;
    int wid = tid >> 5;
    int wm = wid & 1;
    int wn = wid >> 1;

    // per-thread LDG slots: 2 x 16B chunks for A and B each
    const __half* aP[2];
    const __half* bP[2];
    uint32_t stoff[2];
    #pragma unroll
    for (int t = 0; t < 2; t++) {
        int cid = tid + t * 256;          // 0..511
        int row = cid >> 2;               // 0..127
        int c16 = cid & 3;                // 16B chunk (8 halves)
        stoff[t] = (uint32_t)(row * ROWB + c16 * 16);
        int lm = m0 + row;
        int safe = (lm < cnt_e) ? lm : 0;
        if (MODE == 1) {
            int tok = g_rowtok[off_e + safe];
            aP[t] = g_tnh + (size_t)tok * KD + c16 * 8;
        } else {
            aP[t] = g_h1h + (size_t)(off_e + safe) * KD + c16 * 8;
        }
        bP[t] = W + ((size_t)e * NTOT + bn0 + row) * KD + c16 * 8;
    }

    // ldmatrix lane addresses
    uint32_t aoff = (uint32_t)((wm * 64 + (lane & 15)) * ROWB + (lane >> 4) * 16);
    // B x4 covers two adjacent n-blocks
    uint32_t boff = (uint32_t)((wn * 32 + (lane & 7) + (lane >> 4) * 8) * ROWB
                               + ((lane >> 3) & 1) * 16);

    float acc[4][4][4];
    #pragma unroll
    for (int i = 0; i < 4; i++)
        #pragma unroll
        for (int j = 0; j < 4; j++)
            #pragma unroll
            for (int q = 0; q < 4; q++) acc[i][j][q] = 0.f;

    uint4 pA[2], pB[2];
    #pragma unroll
    for (int t = 0; t < 2; t++) {
        pA[t] = *(const uint4*)(aP[t]);
        pB[t] = *(const uint4*)(bP[t]);
    }
    #pragma unroll
    for (int t = 0; t < 2; t++) {
        *(uint4*)(sm + SM_A + stoff[t]) = pA[t];
        *(uint4*)(sm + SM_B + stoff[t]) = pB[t];
    }
    __syncthreads();

    for (int kt = 0; kt < NST; kt++) {
        uint32_t cbuf = sbase + (kt & 1) * BUF_BYTES;
        if (kt + 1 < NST) {
            int kadv = (kt + 1) * 32;
            #pragma unroll
            for (int t = 0; t < 2; t++) {
                pA[t] = *(const uint4*)(aP[t] + kadv);
                pB[t] = *(const uint4*)(bP[t] + kadv);
            }
        }
        #pragma unroll
        for (int ks = 0; ks < 2; ks++) {
            uint32_t ah[4][4];
            #pragma unroll
            for (int im = 0; im < 4; im++)
                ldsm_x4(ah[im], cbuf + SM_A + aoff + im * (16 * ROWB) + ks * 32);
            #pragma unroll
            for (int in2 = 0; in2 < 2; in2++) {
                uint32_t bfr[4];
                ldsm_x4(bfr, cbuf + SM_B + boff + in2 * (16 * ROWB) + ks * 32);
                #pragma unroll
                for (int im = 0; im < 4; im++) {
                    mma16816(acc[im][2*in2],   ah[im], bfr);
                    mma16816(acc[im][2*in2+1], ah[im], bfr + 2);
                }
            }
        }
        if (kt + 1 < NST) {
            char* nb = sm + ((kt + 1) & 1) * BUF_BYTES;
            #pragma unroll
            for (int t = 0; t < 2; t++) {
                *(uint4*)(nb + SM_A + stoff[t]) = pA[t];
                *(uint4*)(nb + SM_B + stoff[t]) = pB[t];
            }
            __syncthreads();
        }
    }

    // ---------------- epilogue ----------------
    #pragma unroll
    for (int im = 0; im < 4; im++) {
        #pragma unroll
        for (int in = 0; in < 4; in++) {
            int r0 = m0 + wm * 64 + im * 16 + (lane >> 2);
            int c  = bn0 + wn * 32 + in * 8 + (lane & 3) * 2;
            const float* bp = bias + (size_t)e * NTOT + c;
            #pragma unroll
            for (int half = 0; half < 2; half++) {
                int r = r0 + half * 8;
                if (r >= cnt_e) continue;
                int p = off_e + r;
                float d0 = acc[im][in][half * 2 + 0];
                float d1 = acc[im][in][half * 2 + 1];
                if (MODE == 1) {
                    float glu = d0 + __ldg(bp);
                    float lin = d1 + __ldg(bp + 1);
                    glu = fminf(glu, 7.0f);
                    lin = fminf(fmaxf(lin, -7.0f), 7.0f);
                    float sig = 1.0f / (1.0f + expf(-1.702f * glu));
                    float h = glu * sig * (lin + 1.0f);
                    g_h1h[(size_t)p * I_DIM + (c >> 1)] = __float2half(h);
                } else {
                    float w = g_roww[p];
                    float o0 = (d0 + __ldg(bp)) * w;
                    float o1 = (d1 + __ldg(bp + 1)) * w;
                    *(float2*)&g_h2[(size_t)p * H_DIM + c] = make_float2(o0, o1);
                }
            }
        }
    }
}

// ---------------- 7: combine ----------------
__global__ __launch_bounds__(256) void combine_kernel(
    const float* __restrict__ x, float* __restrict__ out)
{
    int t = blockIdx.x;
    int tid = threadIdx.x;
    int p0 = g_tokrows[t * TOPK + 0];
    int p1 = g_tokrows[t * TOPK + 1];
    int p2 = g_tokrows[t * TOPK + 2];
    int p3 = g_tokrows[t * TOPK + 3];
    const float4* xr = (const float4*)(x + (size_t)t * H_DIM);
    float4* orow = (float4*)(out + (size_t)t * H_DIM);
    const float4* a = (const float4*)(g_h2 + (size_t)p0 * H_DIM);
    const float4* b = (const float4*)(g_h2 + (size_t)p1 * H_DIM);
    const float4* c = (const float4*)(g_h2 + (size_t)p2 * H_DIM);
    const float4* d = (const float4*)(g_h2 + (size_t)p3 * H_DIM);
    #pragma unroll
    for (int r = 0; r < 2; r++) {
        int f = tid + r * 256;
        float4 v = xr[f];
        float4 q0 = a[f], q1 = b[f], q2 = c[f], q3 = d[f];
        v.x += q0.x + q1.x + q2.x + q3.x;
        v.y += q0.y + q1.y + q2.y + q3.y;
        v.z += q0.z + q1.z + q2.z + q3.z;
        v.w += q0.w + q1.w + q2.w + q3.w;
        orow[f] = v;
    }
}

// ---------------- launch ----------------
extern "C" void kernel_launch(void* const* d_in, const int* in_sizes, int n_in,
                              void* d_out, int out_size)
{
    const float* x     = (const float*)d_in[0];
    const float* scale = (const float*)d_in[1];
    const float* gk    = (const float*)d_in[2];
    const float* gb    = (const float*)d_in[3];
    const float* w1    = (const float*)d_in[4];
    const float* b1    = (const float*)d_in[5];
    const float* w2    = (const float*)d_in[6];
    const float* b2    = (const float*)d_in[7];
    float* out = (float*)d_out;

    __half *w1h, *w2h;
    cudaGetSymbolAddress((void**)&w1h, g_w1h);
    cudaGetSymbolAddress((void**)&w2h, g_w2h);

    cudaFuncSetAttribute(moe_mma_kernel<1>, cudaFuncAttributeMaxDynamicSharedMemorySize, DSMEM);
    cudaFuncSetAttribute(moe_mma_kernel<2>, cudaFuncAttributeMaxDynamicSharedMemorySize, DSMEM);

    init_kernel<<<1, 32>>>();
    rms_router_kernel<<<T_TOK, 256>>>(x, scale, gk, gb);
    scan_kernel<<<1, 32>>>();
    scatter_kernel<<<(T_TOK + 255) / 256, 256>>>();

    int n1 = E_NUM * 2 * I_DIM * H_DIM / 4;
    int n2 = E_NUM * H_DIM * I_DIM / 4;
    convert_kernel<<<n1 / 256, 256>>>(w1, w1h, n1);
    convert_kernel<<<n2 / 256, 256>>>(w2, w2h, n2);

    moe_mma_kernel<1><<<dim3(2 * I_DIM / 128, 80), 256, DSMEM>>>(w1h, b1);
    moe_mma_kernel<2><<<dim3(H_DIM / 128, 80), 256, DSMEM>>>(w2h, b2);
    combine_kernel<<<T_TOK, 256>>>(x, out);
}

// round 7
// speedup vs baseline: 2.5249x; 1.0885x over previous
#include <cuda_runtime.h>
#include <cuda_fp16.h>
#include <math.h>
#include <stdint.h>

#define T_TOK 2048
#define H_DIM 2048
#define I_DIM 2048
#define E_NUM 16
#define TOPK  4
#define ROWS  (T_TOK*TOPK)

// ---------------- scratch ----------------
__device__ __half g_tnh[(size_t)T_TOK * H_DIM];               // 8 MB
__device__ __half g_h1h[(size_t)ROWS * I_DIM];                // 32 MB
__device__ float g_h2[(size_t)ROWS * H_DIM];                  // 64 MB
__device__ int   g_cnt[E_NUM];
__device__ int   g_cnt2[E_NUM];
__device__ int   g_off[E_NUM];
__device__ int   g_rowtok[ROWS];
__device__ float g_roww[ROWS];
__device__ int   g_tokrows[T_TOK * TOPK];
__device__ int   g_topidx[T_TOK * TOPK];
__device__ float g_topw[T_TOK * TOPK];

// ---------------- PTX helpers ----------------
__device__ __forceinline__ uint32_t smem_u32(const void* p) {
    uint32_t a;
    asm("{ .reg .u64 t; cvta.to.shared.u64 t, %1; cvt.u32.u64 %0, t; }" : "=r"(a) : "l"(p));
    return a;
}
__device__ __forceinline__ void ldsm_x4(uint32_t* r, uint32_t addr) {
    asm volatile("ldmatrix.sync.aligned.m8n8.x4.shared.b16 {%0,%1,%2,%3}, [%4];"
                 : "=r"(r[0]), "=r"(r[1]), "=r"(r[2]), "=r"(r[3]) : "r"(addr));
}
__device__ __forceinline__ void mma16816(float* d, const uint32_t* a, const uint32_t* b) {
    asm volatile("mma.sync.aligned.m16n8k16.row.col.f32.f16.f16.f32 "
                 "{%0,%1,%2,%3}, {%4,%5,%6,%7}, {%8,%9}, {%0,%1,%2,%3};"
                 : "+f"(d[0]), "+f"(d[1]), "+f"(d[2]), "+f"(d[3])
                 : "r"(a[0]), "r"(a[1]), "r"(a[2]), "r"(a[3]), "r"(b[0]), "r"(b[1]));
}
// pack two fp32 -> fp16x2 register
__device__ __forceinline__ uint32_t pkh2(float a, float b) {
    __half2 h = __floats2half2_rn(a, b);
    return *(uint32_t*)&h;
}

// ---------------- 0: init ----------------
__global__ void init_kernel() {
    int i = threadIdx.x;
    if (i < E_NUM) { g_cnt[i] = 0; g_cnt2[i] = 0; }
}

// ---------------- 1: fused RMSNorm + router (writes fp16) ----------------
__global__ __launch_bounds__(256) void rms_router_kernel(
    const float* __restrict__ x, const float* __restrict__ scale,
    const float* __restrict__ gk, const float* __restrict__ gb)
{
    int t = blockIdx.x;
    int tid = threadIdx.x;
    const float* xr = x + (size_t)t * H_DIM;

    float4 v0 = *(const float4*)(xr + tid * 8);
    float4 v1 = *(const float4*)(xr + tid * 8 + 4);
    float ss = v0.x*v0.x + v0.y*v0.y + v0.z*v0.z + v0.w*v0.w
             + v1.x*v1.x + v1.y*v1.y + v1.z*v1.z + v1.w*v1.w;
    #pragma unroll
    for (int o = 16; o > 0; o >>= 1) ss += __shfl_down_sync(0xffffffffu, ss, o);
    __shared__ float warpsum[8];
    __shared__ float s_r;
    if ((tid & 31) == 0) warpsum[tid >> 5] = ss;
    __syncthreads();
    if (tid == 0) {
        float tot = 0.f;
        #pragma unroll
        for (int w = 0; w < 8; w++) tot += warpsum[w];
        s_r = 1.0f / sqrtf(tot / (float)H_DIM + 1e-5f);
    }
    __syncthreads();
    float r = s_r;

    float4 sc0 = *(const float4*)(scale + tid * 8);
    float4 sc1 = *(const float4*)(scale + tid * 8 + 4);
    float tn[8];
    tn[0] = v0.x*r*sc0.x; tn[1] = v0.y*r*sc0.y; tn[2] = v0.z*r*sc0.z; tn[3] = v0.w*r*sc0.w;
    tn[4] = v1.x*r*sc1.x; tn[5] = v1.y*r*sc1.y; tn[6] = v1.z*r*sc1.z; tn[7] = v1.w*r*sc1.w;

    __half hh[8];
    #pragma unroll
    for (int u = 0; u < 8; u++) hh[u] = __float2half(tn[u]);
    *(uint4*)(g_tnh + (size_t)t * H_DIM + tid * 8) = *(uint4*)hh;

    float ge[E_NUM];
    #pragma unroll
    for (int e = 0; e < E_NUM; e++) ge[e] = 0.f;
    #pragma unroll
    for (int u = 0; u < 8; u++) {
        const float4* wrow = (const float4*)(gk + (size_t)(tid * 8 + u) * E_NUM);
        float tv = tn[u];
        float4 a = wrow[0], b = wrow[1], c = wrow[2], d = wrow[3];
        ge[0]+=tv*a.x; ge[1]+=tv*a.y; ge[2]+=tv*a.z; ge[3]+=tv*a.w;
        ge[4]+=tv*b.x; ge[5]+=tv*b.y; ge[6]+=tv*b.z; ge[7]+=tv*b.w;
        ge[8]+=tv*c.x; ge[9]+=tv*c.y; ge[10]+=tv*c.z; ge[11]+=tv*c.w;
        ge[12]+=tv*d.x; ge[13]+=tv*d.y; ge[14]+=tv*d.z; ge[15]+=tv*d.w;
    }
    #pragma unroll
    for (int o = 16; o > 0; o >>= 1) {
        #pragma unroll
        for (int e = 0; e < E_NUM; e++) ge[e] += __shfl_down_sync(0xffffffffu, ge[e], o);
    }
    __shared__ float sg[8][E_NUM];
    if ((tid & 31) == 0) {
        #pragma unroll
        for (int e = 0; e < E_NUM; e++) sg[tid >> 5][e] = ge[e];
    }
    __syncthreads();
    __shared__ float s_logit[E_NUM];
    if (tid < E_NUM) {
        float v = gb[tid];
        #pragma unroll
        for (int w = 0; w < 8; w++) v += sg[w][tid];
        s_logit[tid] = v;
    }
    __syncthreads();
    if (tid == 0) {
        float vals[E_NUM];
        #pragma unroll
        for (int e = 0; e < E_NUM; e++) vals[e] = s_logit[e];
        int ids[TOPK]; float tv[TOPK];
        #pragma unroll
        for (int k = 0; k < TOPK; k++) {
            int bi = 0; float bv = -1e30f;
            #pragma unroll
            for (int e = 0; e < E_NUM; e++) if (vals[e] > bv) { bv = vals[e]; bi = e; }
            ids[k] = bi; tv[k] = bv; vals[bi] = -1e30f;
        }
        float m = tv[0], ex[TOPK], s = 0.f;
        #pragma unroll
        for (int k = 0; k < TOPK; k++) { ex[k] = expf(tv[k] - m); s += ex[k]; }
        float inv = 1.0f / s;
        #pragma unroll
        for (int k = 0; k < TOPK; k++) {
            g_topidx[t * TOPK + k] = ids[k];
            g_topw[t * TOPK + k]   = ex[k] * inv;
            atomicAdd(&g_cnt[ids[k]], 1);
        }
    }
}

// ---------------- 2/3: scan + scatter ----------------
__global__ void scan_kernel() {
    if (threadIdx.x == 0) {
        int acc = 0;
        for (int e = 0; e < E_NUM; e++) { g_off[e] = acc; acc += g_cnt[e]; g_cnt2[e] = 0; }
    }
}
__global__ void scatter_kernel() {
    int t = blockIdx.x * blockDim.x + threadIdx.x;
    if (t >= T_TOK) return;
    #pragma unroll
    for (int k = 0; k < TOPK; k++) {
        int e = g_topidx[t * TOPK + k];
        int pos = g_off[e] + atomicAdd(&g_cnt2[e], 1);
        g_rowtok[pos] = t;
        g_roww[pos]   = g_topw[t * TOPK + k];
        g_tokrows[t * TOPK + k] = pos;
    }
}

// ---------------- 4/5: grouped GEMMs via mma.sync fp16; W read fp32, converted in-loop ----------------
// Tile 128x128x32.  8 warps 2(m) x 4(n), warp tile 64x32. 32 HMMA/warp/stage.
// Per-buffer: A [0,10240)  B [10240,20480). Pitch 80B. Double-buffered.
#define ROWB 80
#define SM_A 0
#define SM_B 10240
#define BUF_BYTES 20480
#define DSMEM (2 * BUF_BYTES)

template <int MODE>
__global__ __launch_bounds__(256) void moe_mma_kernel(
    const float* __restrict__ W, const float* __restrict__ bias)
{
    constexpr int NTOT = (MODE == 1) ? 2 * I_DIM : H_DIM;
    constexpr int KD = 2048;
    constexpr int NST = KD / 32;   // 64 stages

    int mt = blockIdx.y;
    int e = -1, cnt_e = 0, off_e = 0, acc0 = 0;
    #pragma unroll
    for (int ee = 0; ee < E_NUM; ee++) {
        int c = g_cnt[ee];
        int tl = (c + 127) >> 7;
        if (e < 0) {
            if (mt < acc0 + tl) { e = ee; cnt_e = c; off_e = g_off[ee]; mt -= acc0; }
            else acc0 += tl;
        }
    }
    if (e < 0) return;
    int m0 = mt * 128;
    int bn0 = blockIdx.x * 128;

    extern __shared__ __align__(16) char sm[];
    uint32_t sbase = smem_u32(sm);

    int tid = threadIdx.x;
    int lane = tid & 31;
    int wid = tid >> 5;
    int wm = wid & 1;
    int wn = wid >> 1;

    // per-thread LDG slots: 2 chunks; A fp16 16B, B fp32 2x16B (converted to 16B fp16)
    const __half* aP[2];
    const float* bP[2];
    uint32_t stoff[2];
    #pragma unroll
    for (int t = 0; t < 2; t++) {
        int cid = tid + t * 256;          // 0..511
        int row = cid >> 2;               // 0..127
        int c16 = cid & 3;                // chunk of 8 elements
        stoff[t] = (uint32_t)(row * ROWB + c16 * 16);
        int lm = m0 + row;
        int safe = (lm < cnt_e) ? lm : 0;
        if (MODE == 1) {
            int tok = g_rowtok[off_e + safe];
            aP[t] = g_tnh + (size_t)tok * KD + c16 * 8;
        } else {
            aP[t] = g_h1h + (size_t)(off_e + safe) * KD + c16 * 8;
        }
        bP[t] = W + ((size_t)e * NTOT + bn0 + row) * KD + c16 * 8;
    }

    // ldmatrix lane addresses
    uint32_t aoff = (uint32_t)((wm * 64 + (lane & 15)) * ROWB + (lane >> 4) * 16);
    uint32_t boff = (uint32_t)((wn * 32 + (lane & 7) + (lane >> 4) * 8) * ROWB
                               + ((lane >> 3) & 1) * 16);

    float acc[4][4][4];
    #pragma unroll
    for (int i = 0; i < 4; i++)
        #pragma unroll
        for (int j = 0; j < 4; j++)
            #pragma unroll
            for (int q = 0; q < 4; q++) acc[i][j][q] = 0.f;

    uint4 pA[2];
    float4 pB0[2], pB1[2];
    #pragma unroll
    for (int t = 0; t < 2; t++) {
        pA[t]  = *(const uint4*)(aP[t]);
        pB0[t] = *(const float4*)(bP[t]);
        pB1[t] = *(const float4*)(bP[t] + 4);
    }
    #pragma unroll
    for (int t = 0; t < 2; t++) {
        *(uint4*)(sm + SM_A + stoff[t]) = pA[t];
        uint4 bh;
        bh.x = pkh2(pB0[t].x, pB0[t].y);
        bh.y = pkh2(pB0[t].z, pB0[t].w);
        bh.z = pkh2(pB1[t].x, pB1[t].y);
        bh.w = pkh2(pB1[t].z, pB1[t].w);
        *(uint4*)(sm + SM_B + stoff[t]) = bh;
    }
    __syncthreads();

    for (int kt = 0; kt < NST; kt++) {
        uint32_t cbuf = sbase + (kt & 1) * BUF_BYTES;
        if (kt + 1 < NST) {
            int kadv = (kt + 1) * 32;
            #pragma unroll
            for (int t = 0; t < 2; t++) {
                pA[t]  = *(const uint4*)(aP[t] + kadv);
                pB0[t] = *(const float4*)(bP[t] + kadv);
                pB1[t] = *(const float4*)(bP[t] + kadv + 4);
            }
        }
        #pragma unroll
        for (int ks = 0; ks < 2; ks++) {
            uint32_t ah[4][4];
            #pragma unroll
            for (int im = 0; im < 4; im++)
                ldsm_x4(ah[im], cbuf + SM_A + aoff + im * (16 * ROWB) + ks * 32);
            #pragma unroll
            for (int in2 = 0; in2 < 2; in2++) {
                uint32_t bfr[4];
                ldsm_x4(bfr, cbuf + SM_B + boff + in2 * (16 * ROWB) + ks * 32);
                #pragma unroll
                for (int im = 0; im < 4; im++) {
                    mma16816(acc[im][2*in2],   ah[im], bfr);
                    mma16816(acc[im][2*in2+1], ah[im], bfr + 2);
                }
            }
        }
        if (kt + 1 < NST) {
            char* nb = sm + ((kt + 1) & 1) * BUF_BYTES;
            #pragma unroll
            for (int t = 0; t < 2; t++) {
                *(uint4*)(nb + SM_A + stoff[t]) = pA[t];
                uint4 bh;
                bh.x = pkh2(pB0[t].x, pB0[t].y);
                bh.y = pkh2(pB0[t].z, pB0[t].w);
                bh.z = pkh2(pB1[t].x, pB1[t].y);
                bh.w = pkh2(pB1[t].z, pB1[t].w);
                *(uint4*)(nb + SM_B + stoff[t]) = bh;
            }
            __syncthreads();
        }
    }

    // ---------------- epilogue ----------------
    #pragma unroll
    for (int im = 0; im < 4; im++) {
        #pragma unroll
        for (int in = 0; in < 4; in++) {
            int r0 = m0 + wm * 64 + im * 16 + (lane >> 2);
            int c  = bn0 + wn * 32 + in * 8 + (lane & 3) * 2;
            const float* bp = bias + (size_t)e * NTOT + c;
            #pragma unroll
            for (int half = 0; half < 2; half++) {
                int r = r0 + half * 8;
                if (r >= cnt_e) continue;
                int p = off_e + r;
                float d0 = acc[im][in][half * 2 + 0];
                float d1 = acc[im][in][half * 2 + 1];
                if (MODE == 1) {
                    float glu = d0 + __ldg(bp);
                    float lin = d1 + __ldg(bp + 1);
                    glu = fminf(glu, 7.0f);
                    lin = fminf(fmaxf(lin, -7.0f), 7.0f);
                    float sig = 1.0f / (1.0f + expf(-1.702f * glu));
                    float h = glu * sig * (lin + 1.0f);
                    g_h1h[(size_t)p * I_DIM + (c >> 1)] = __float2half(h);
                } else {
                    float w = g_roww[p];
                    float o0 = (d0 + __ldg(bp)) * w;
                    float o1 = (d1 + __ldg(bp + 1)) * w;
                    *(float2*)&g_h2[(size_t)p * H_DIM + c] = make_float2(o0, o1);
                }
            }
        }
    }
}

// ---------------- 6: combine ----------------
__global__ __launch_bounds__(256) void combine_kernel(
    const float* __restrict__ x, float* __restrict__ out)
{
    int t = blockIdx.x;
    int tid = threadIdx.x;
    int p0 = g_tokrows[t * TOPK + 0];
    int p1 = g_tokrows[t * TOPK + 1];
    int p2 = g_tokrows[t * TOPK + 2];
    int p3 = g_tokrows[t * TOPK + 3];
    const float4* xr = (const float4*)(x + (size_t)t * H_DIM);
    float4* orow = (float4*)(out + (size_t)t * H_DIM);
    const float4* a = (const float4*)(g_h2 + (size_t)p0 * H_DIM);
    const float4* b = (const float4*)(g_h2 + (size_t)p1 * H_DIM);
    const float4* c = (const float4*)(g_h2 + (size_t)p2 * H_DIM);
    const float4* d = (const float4*)(g_h2 + (size_t)p3 * H_DIM);
    #pragma unroll
    for (int r = 0; r < 2; r++) {
        int f = tid + r * 256;
        float4 v = xr[f];
        float4 q0 = a[f], q1 = b[f], q2 = c[f], q3 = d[f];
        v.x += q0.x + q1.x + q2.x + q3.x;
        v.y += q0.y + q1.y + q2.y + q3.y;
        v.z += q0.z + q1.z + q2.z + q3.z;
        v.w += q0.w + q1.w + q2.w + q3.w;
        orow[f] = v;
    }
}

// ---------------- launch ----------------
extern "C" void kernel_launch(void* const* d_in, const int* in_sizes, int n_in,
                              void* d_out, int out_size)
{
    const float* x     = (const float*)d_in[0];
    const float* scale = (const float*)d_in[1];
    const float* gk    = (const float*)d_in[2];
    const float* gb    = (const float*)d_in[3];
    const float* w1    = (const float*)d_in[4];
    const float* b1    = (const float*)d_in[5];
    const float* w2    = (const float*)d_in[6];
    const float* b2    = (const float*)d_in[7];
    float* out = (float*)d_out;

    cudaFuncSetAttribute(moe_mma_kernel<1>, cudaFuncAttributeMaxDynamicSharedMemorySize, DSMEM);
    cudaFuncSetAttribute(moe_mma_kernel<2>, cudaFuncAttributeMaxDynamicSharedMemorySize, DSMEM);

    init_kernel<<<1, 32>>>();
    rms_router_kernel<<<T_TOK, 256>>>(x, scale, gk, gb);
    scan_kernel<<<1, 32>>>();
    scatter_kernel<<<(T_TOK + 255) / 256, 256>>>();
    moe_mma_kernel<1><<<dim3(2 * I_DIM / 128, 80), 256, DSMEM>>>(w1, b1);
    moe_mma_kernel<2><<<dim3(H_DIM / 128, 80), 256, DSMEM>>>(w2, b2);
    combine_kernel<<<T_TOK, 256>>>(x, out);
}